// round 3
// baseline (speedup 1.0000x reference)
#include <cuda_runtime.h>

// ---------------------------------------------------------------------------
// GroupedQueryAttention, restructured:
//   x_embed affine in scalar x[b,s] => K[b,s,j] = x*kwf[j] + kc[s,j]
//   score (log2 domain) = a[g,p]*x[b,s] + bconst[g,p,s]   (exp2-safe, no max)
//   ctx = invZ * ( sum_s e*vc[s,:] + (sum_s e*x) * vw )
//   out = ctx @ o_w + o_b
// Pair p in [0,32) per group g: r=p>>3, q=p&7, head h=g*4+r.
// k_main: 512 thr / 16 warps; warp wp owns pairs (2wp, 2wp+1) over FULL s.
// Batches NB=2 consecutive b rows per chunk so the b-invariant table LDS
// (bconst + vc) amortizes across the batch. Two passes: pass1 accumulates
// Z/xs/ctx (e transient); pass2 recomputes e and stores attn via STG.64.
// Grid (74,2): 148 CTAs = one full wave; 512 chunks split 6/7 per CTA.
// ---------------------------------------------------------------------------

#define LOG2E_OVER_SCALE ((float)(1.4426950408889634 / 2.8284271247461903))

// table layouts built for LDS.128:
//  g_bconst4[g][wp][s2][4] = { b(2s2,p0), b(2s2,p1), b(2s2+1,p0), b(2s2+1,p1) }
//  g_vc4[g][jj][s2][4]     = { vc(2s2,2jj), vc(2s2,2jj+1), vc(2s2+1,2jj), vc(2s2+1,2jj+1) }
__device__ __align__(16) float g_bconst4[2][16][512][4];  // 256 KB
__device__ __align__(16) float g_vc4[2][4][512][4];       // 64 KB
__device__ float g_a[2][32];
__device__ float g_vw[2][8];
__device__ __align__(16) float g_ctx[1024][8][64];        // 2 MB scratch

__device__ __forceinline__ float ex2f(float x) {
    float r; asm("ex2.approx.ftz.f32 %0, %1;" : "=f"(r) : "f"(x)); return r;
}
__device__ __forceinline__ unsigned long long pack2(float a, float b) {
    unsigned long long r; asm("mov.b64 %0, {%1, %2};" : "=l"(r) : "f"(a), "f"(b)); return r;
}
__device__ __forceinline__ void unpack2(unsigned long long v, float& a, float& b) {
    asm("mov.b64 {%0, %1}, %2;" : "=f"(a), "=f"(b) : "l"(v));
}
__device__ __forceinline__ void fma2(unsigned long long& d, unsigned long long a, unsigned long long b) {
    asm("fma.rn.f32x2 %0, %1, %2, %0;" : "+l"(d) : "l"(a), "l"(b));
}
__device__ __forceinline__ float wsum(float v) {
#pragma unroll
    for (int m = 16; m > 0; m >>= 1) v += __shfl_xor_sync(0xffffffffu, v, m);
    return v;
}

// --- precompute 1: a[g][p] (x-coefficient of logits), vw -------------------
__global__ void k_pre1(const float* __restrict__ fe_w, const float* __restrict__ k_w,
                       const float* __restrict__ v_w, const float* __restrict__ queries) {
    __shared__ float kw[16];
    int t = threadIdx.x;  // 64 threads
    if (t < 16) {
        float sk = 0.f, sv = 0.f;
        for (int d = 0; d < 64; d++) {
            sk = fmaf(fe_w[d], k_w[d * 16 + t], sk);
            sv = fmaf(fe_w[d], v_w[d * 16 + t], sv);
        }
        kw[t] = sk;
        g_vw[t >> 3][t & 7] = sv;
    }
    __syncthreads();
    int g = t >> 5, p = t & 31, r = p >> 3, q = p & 7, h = g * 4 + r;
    float s = 0.f;
#pragma unroll
    for (int j = 0; j < 8; j++) s = fmaf(queries[q * 64 + h * 8 + j], kw[g * 8 + j], s);
    g_a[g][p] = s * LOG2E_OVER_SCALE;
}

// --- precompute 2 (fused): kc/vc per s, then bconst ------------------------
__global__ __launch_bounds__(256) void k_pre2(
        const float* __restrict__ fe_b, const float* __restrict__ pos_emb,
        const float* __restrict__ k_w, const float* __restrict__ k_b,
        const float* __restrict__ v_w, const float* __restrict__ v_b,
        const float* __restrict__ queries) {
    __shared__ float sk[16][16];   // kc for 16 local s
    int t = threadIdx.x;
    int s0 = blockIdx.x * 16;      // even
    {   // phase 1: (s_local, j) per thread
        int sl = t >> 4, j = t & 15;
        int s = s0 + sl;
        float kc = k_b[j], vc = v_b[j];
        for (int d = 0; d < 64; d++) {
            float e = fe_b[d] + pos_emb[s * 64 + d];
            kc = fmaf(e, k_w[d * 16 + j], kc);
            vc = fmaf(e, v_w[d * 16 + j], vc);
        }
        sk[sl][j] = kc;
        g_vc4[j >> 3][(j & 7) >> 1][s >> 1][(s & 1) * 2 + (j & 1)] = vc;
    }
    __syncthreads();
    // phase 2: 16 s * 64 pairs = 1024 items, 4 per thread
#pragma unroll
    for (int u = 0; u < 4; u++) {
        int item = t + 256 * u;
        int sl = item >> 6, pp = item & 63;
        int g = pp >> 5, p = pp & 31, r = p >> 3, q = p & 7, h = g * 4 + r;
        int s = s0 + sl;
        float acc = 0.f;
#pragma unroll
        for (int j = 0; j < 8; j++) acc = fmaf(queries[q * 64 + h * 8 + j], sk[sl][g * 8 + j], acc);
        g_bconst4[g][p >> 1][s >> 1][(s & 1) * 2 + (p & 1)] = acc * LOG2E_OVER_SCALE;
    }
}

// --- main: softmax + attn store + ctx ---------------------------------------
__global__ __launch_bounds__(512, 1) void k_main(const float* __restrict__ x,
                                                 float* __restrict__ attn_out) {
    extern __shared__ float smem[];
    float4* sm_b4 = (float4*)smem;                        // [16][512] f4 = 128KB
    float4* sm_vc4 = (float4*)(smem + 32768);             // [4][512]  f4 = 32KB
    float2* sm_x2 = (float2*)(smem + 32768 + 8192);       // [2][512]  f2 = 8KB
    const int g = blockIdx.y;
    const int tid = threadIdx.x;

    {   // cache group tables in smem once per CTA
        const float4* src = (const float4*)&g_bconst4[g][0][0][0];
#pragma unroll
        for (int i = 0; i < 16; i++) sm_b4[tid + 512 * i] = src[tid + 512 * i];
        const float4* vs = (const float4*)&g_vc4[g][0][0][0];
#pragma unroll
        for (int i = 0; i < 4; i++) sm_vc4[tid + 512 * i] = vs[tid + 512 * i];
    }

    const int w = tid >> 5, lane = tid & 31;
    const int p0 = 2 * w, p1 = p0 + 1;
    const float a0 = g_a[g][p0], a1 = g_a[g][p1];
    const int h0 = g * 4 + (p0 >> 3), q0 = p0 & 7;
    const int h1 = g * 4 + (p1 >> 3), q1 = p1 & 7;
    float vwj[8];
#pragma unroll
    for (int j = 0; j < 8; j++) vwj[j] = g_vw[g][j];

    for (int c = blockIdx.x; c < 512; c += 74) {
        const int b0 = 2 * c;  // batch rows b0, b0+1
        __syncthreads();       // protect sm_x2 reuse (pass2 readers done)
        {   // both x rows contiguous: one coalesced 8KB copy
            const float4* xsrc = (const float4*)(x + b0 * 1024);
            ((float4*)sm_x2)[tid] = xsrc[tid];
        }
        __syncthreads();

        // ---------------- pass 1: accumulate Z, xs, ctx ----------------
        float z0a = 0.f, z1a = 0.f, xs0a = 0.f, xs1a = 0.f;
        float z0b = 0.f, z1b = 0.f, xs0b = 0.f, xs1b = 0.f;
        unsigned long long c0a[4], c1a[4], c0b[4], c1b[4];
#pragma unroll
        for (int k = 0; k < 4; k++) { c0a[k] = c1a[k] = c0b[k] = c1b[k] = 0ull; }

#pragma unroll
        for (int i = 0; i < 16; i++) {
            int s2 = lane + 32 * i;
            float4 bb = sm_b4[w * 512 + s2];
            float2 xA = sm_x2[s2];
            float2 xB = sm_x2[512 + s2];

            float e00 = ex2f(fmaf(a0, xA.x, bb.x));
            float e10 = ex2f(fmaf(a1, xA.x, bb.y));
            float e01 = ex2f(fmaf(a0, xA.y, bb.z));
            float e11 = ex2f(fmaf(a1, xA.y, bb.w));
            float f00 = ex2f(fmaf(a0, xB.x, bb.x));
            float f10 = ex2f(fmaf(a1, xB.x, bb.y));
            float f01 = ex2f(fmaf(a0, xB.y, bb.z));
            float f11 = ex2f(fmaf(a1, xB.y, bb.w));

            z0a += e00 + e01; z1a += e10 + e11;
            z0b += f00 + f01; z1b += f10 + f11;
            xs0a = fmaf(e00, xA.x, fmaf(e01, xA.y, xs0a));
            xs1a = fmaf(e10, xA.x, fmaf(e11, xA.y, xs1a));
            xs0b = fmaf(f00, xB.x, fmaf(f01, xB.y, xs0b));
            xs1b = fmaf(f10, xB.x, fmaf(f11, xB.y, xs1b));

            unsigned long long pe00 = pack2(e00, e00), pe01 = pack2(e01, e01);
            unsigned long long pe10 = pack2(e10, e10), pe11 = pack2(e11, e11);
            unsigned long long pf00 = pack2(f00, f00), pf01 = pack2(f01, f01);
            unsigned long long pf10 = pack2(f10, f10), pf11 = pack2(f11, f11);
#pragma unroll
            for (int k = 0; k < 4; k++) {
                float4 v4 = sm_vc4[k * 512 + s2];
                unsigned long long vlo = pack2(v4.x, v4.y);
                unsigned long long vhi = pack2(v4.z, v4.w);
                fma2(c0a[k], pe00, vlo); fma2(c0a[k], pe01, vhi);
                fma2(c1a[k], pe10, vlo); fma2(c1a[k], pe11, vhi);
                fma2(c0b[k], pf00, vlo); fma2(c0b[k], pf01, vhi);
                fma2(c1b[k], pf10, vlo); fma2(c1b[k], pf11, vhi);
            }
        }

        // ---------------- warp-local reductions ----------------
        z0a = wsum(z0a); z1a = wsum(z1a); xs0a = wsum(xs0a); xs1a = wsum(xs1a);
        z0b = wsum(z0b); z1b = wsum(z1b); xs0b = wsum(xs0b); xs1b = wsum(xs1b);
        float cf0a[8], cf1a[8], cf0b[8], cf1b[8];
#pragma unroll
        for (int k = 0; k < 4; k++) {
            unpack2(c0a[k], cf0a[2 * k], cf0a[2 * k + 1]);
            unpack2(c1a[k], cf1a[2 * k], cf1a[2 * k + 1]);
            unpack2(c0b[k], cf0b[2 * k], cf0b[2 * k + 1]);
            unpack2(c1b[k], cf1b[2 * k], cf1b[2 * k + 1]);
        }
#pragma unroll
        for (int j = 0; j < 8; j++) {
            cf0a[j] = wsum(cf0a[j]); cf1a[j] = wsum(cf1a[j]);
            cf0b[j] = wsum(cf0b[j]); cf1b[j] = wsum(cf1b[j]);
        }

        const float invZ0a = 1.0f / z0a, invZ1a = 1.0f / z1a;
        const float invZ0b = 1.0f / z0b, invZ1b = 1.0f / z1b;

        if (lane == 0) {
#pragma unroll
            for (int j = 0; j < 8; j++) {
                g_ctx[b0][q0][h0 * 8 + j]     = invZ0a * fmaf(xs0a, vwj[j], cf0a[j]);
                g_ctx[b0][q1][h1 * 8 + j]     = invZ1a * fmaf(xs1a, vwj[j], cf1a[j]);
                g_ctx[b0 + 1][q0][h0 * 8 + j] = invZ0b * fmaf(xs0b, vwj[j], cf0b[j]);
                g_ctx[b0 + 1][q1][h1 * 8 + j] = invZ1b * fmaf(xs1b, vwj[j], cf1b[j]);
            }
        }

        // ---------------- pass 2: recompute e, store attn --------------
        float2* o0a = (float2*)(attn_out + (((size_t)b0 * 8 + h0) * 8 + q0) * 1024) + lane;
        float2* o1a = (float2*)(attn_out + (((size_t)b0 * 8 + h1) * 8 + q1) * 1024) + lane;
        float2* o0b = (float2*)(attn_out + (((size_t)(b0 + 1) * 8 + h0) * 8 + q0) * 1024) + lane;
        float2* o1b = (float2*)(attn_out + (((size_t)(b0 + 1) * 8 + h1) * 8 + q1) * 1024) + lane;
#pragma unroll
        for (int i = 0; i < 16; i++) {
            int s2 = lane + 32 * i;
            float4 bb = sm_b4[w * 512 + s2];
            float2 xA = sm_x2[s2];
            float2 xB = sm_x2[512 + s2];
            float2 r;
            r.x = ex2f(fmaf(a0, xA.x, bb.x)) * invZ0a;
            r.y = ex2f(fmaf(a0, xA.y, bb.z)) * invZ0a;
            o0a[i * 32] = r;
            r.x = ex2f(fmaf(a1, xA.x, bb.y)) * invZ1a;
            r.y = ex2f(fmaf(a1, xA.y, bb.w)) * invZ1a;
            o1a[i * 32] = r;
            r.x = ex2f(fmaf(a0, xB.x, bb.x)) * invZ0b;
            r.y = ex2f(fmaf(a0, xB.y, bb.z)) * invZ0b;
            o0b[i * 32] = r;
            r.x = ex2f(fmaf(a1, xB.x, bb.y)) * invZ1b;
            r.y = ex2f(fmaf(a1, xB.y, bb.w)) * invZ1b;
            o1b[i * 32] = r;
        }
    }
}

// --- epilogue: out = ctx @ o_w + o_b (persistent, o_w loaded once) ----------
__global__ __launch_bounds__(512) void k_epilogue(const float* __restrict__ o_w,
                                                  const float* __restrict__ o_b,
                                                  float* __restrict__ out) {
    __shared__ float sw[4096];      // o_w 64x64
    __shared__ float sc[2][512];    // double-buffered ctx row
    int t = threadIdx.x;
#pragma unroll
    for (int i = 0; i < 8; i++) sw[t + 512 * i] = o_w[t + 512 * i];
    const int q = t >> 6, e = t & 63;
    const float bias = o_b[e];
    int buf = 0;
    for (int b = blockIdx.x; b < 1024; b += 148) {
        sc[buf][t] = ((const float*)g_ctx)[b * 512 + t];
        __syncthreads();
        float acc = bias;
#pragma unroll
        for (int f = 0; f < 64; f++) acc = fmaf(sc[buf][q * 64 + f], sw[f * 64 + e], acc);
        out[(size_t)b * 512 + t] = acc;
        buf ^= 1;
    }
}

// ---------------------------------------------------------------------------
extern "C" void kernel_launch(void* const* d_in, const int* in_sizes, int n_in,
                              void* d_out, int out_size) {
    const float* x       = (const float*)d_in[0];
    const float* queries = (const float*)d_in[1];
    const float* fe_w    = (const float*)d_in[2];
    const float* fe_b    = (const float*)d_in[3];
    const float* pos_emb = (const float*)d_in[4];
    const float* k_w     = (const float*)d_in[5];
    const float* k_b     = (const float*)d_in[6];
    const float* v_w     = (const float*)d_in[7];
    const float* v_b     = (const float*)d_in[8];
    const float* o_w     = (const float*)d_in[9];
    const float* o_b     = (const float*)d_in[10];

    float* out  = (float*)d_out;                 // [1024, 512]
    float* attn = out + 1024 * 512;              // [1024, 8, 8, 1024]

    int smem_bytes = (32768 + 8192 + 2048) * 4;  // 172,032 B
    cudaFuncSetAttribute(k_main, cudaFuncAttributeMaxDynamicSharedMemorySize, smem_bytes);

    k_pre1<<<1, 64>>>(fe_w, k_w, v_w, queries);
    k_pre2<<<64, 256>>>(fe_b, pos_emb, k_w, k_b, v_w, v_b, queries);
    k_main<<<dim3(74, 2), 512, smem_bytes>>>(x, attn);
    k_epilogue<<<148, 512>>>(o_w, o_b, out);
}

// round 4
// speedup vs baseline: 1.3928x; 1.3928x over previous
#include <cuda_runtime.h>

// ---------------------------------------------------------------------------
// GroupedQueryAttention:
//   x_embed affine in scalar x[b,s] => score(log2) = a[g,p]*x[b,s] + bconst[g,p,s]
//   attn = e/Z ; ctx = invZ*(sum_s e*vc[s,:] + (sum_s e*x)*vw) ; out = ctx@o_w+o_b
// k_main: 1024 thr (32 warps), grid 148 = one wave. Warp w: g=w>>4, wp=w&15,
// pairs p0=2wp,p1=2wp+1, full s-range (lane owns s=2*(32i+lane)+{0,1}).
// Z for b+148 is computed in the SAME inner loop as the main work for b
// (shares the bconst load), so e never needs storing => ~55 regs, no spills.
// bconst comes from GLOBAL (L1/L2), vc + x + o_w live in smem.
// Out-projection is fused (per-b ctx staged through smem). No epilogue kernel.
// ---------------------------------------------------------------------------

#define LOG2E_OVER_SCALE ((float)(1.4426950408889634 / 2.8284271247461903))

// g_b4[g][wp][s2][4] = { b(2s2,p0), b(2s2,p1), b(2s2+1,p0), b(2s2+1,p1) }
__device__ __align__(16) float g_b4[2][16][512][4];   // 256 KB
// g_vc4[g][jj][s2][4] = { vc(2s2,2jj), vc(2s2,2jj+1), vc(2s2+1,2jj), vc(2s2+1,2jj+1) }
__device__ __align__(16) float g_vc4[2][4][512][4];   // 64 KB
__device__ float g_a[2][32];
__device__ float g_vw[2][8];

__device__ __forceinline__ float ex2f(float x) {
    float r; asm("ex2.approx.ftz.f32 %0, %1;" : "=f"(r) : "f"(x)); return r;
}
__device__ __forceinline__ unsigned long long pack2(float a, float b) {
    unsigned long long r; asm("mov.b64 %0, {%1, %2};" : "=l"(r) : "f"(a), "f"(b)); return r;
}
__device__ __forceinline__ void unpack2(unsigned long long v, float& a, float& b) {
    asm("mov.b64 {%0, %1}, %2;" : "=f"(a), "=f"(b) : "l"(v));
}
__device__ __forceinline__ void fma2(unsigned long long& d, unsigned long long a, unsigned long long b) {
    asm("fma.rn.f32x2 %0, %1, %2, %0;" : "+l"(d) : "l"(a), "l"(b));
}
__device__ __forceinline__ float wsum(float v) {
#pragma unroll
    for (int m = 16; m > 0; m >>= 1) v += __shfl_xor_sync(0xffffffffu, v, m);
    return v;
}

// --- precompute 1: a[g][p], vw ----------------------------------------------
__global__ void k_pre1(const float* __restrict__ fe_w, const float* __restrict__ k_w,
                       const float* __restrict__ v_w, const float* __restrict__ queries) {
    __shared__ float kw[16];
    int t = threadIdx.x;  // 64
    if (t < 16) {
        float sk = 0.f, sv = 0.f;
        for (int d = 0; d < 64; d++) {
            sk = fmaf(fe_w[d], k_w[d * 16 + t], sk);
            sv = fmaf(fe_w[d], v_w[d * 16 + t], sv);
        }
        kw[t] = sk;
        g_vw[t >> 3][t & 7] = sv;
    }
    __syncthreads();
    int g = t >> 5, p = t & 31, r = p >> 3, q = p & 7, h = g * 4 + r;
    float s = 0.f;
#pragma unroll
    for (int j = 0; j < 8; j++) s = fmaf(queries[q * 64 + h * 8 + j], kw[g * 8 + j], s);
    g_a[g][p] = s * LOG2E_OVER_SCALE;
}

// --- precompute 2 (fused): kc/vc per s, then bconst --------------------------
__global__ __launch_bounds__(256) void k_pre2(
        const float* __restrict__ fe_b, const float* __restrict__ pos_emb,
        const float* __restrict__ k_w, const float* __restrict__ k_b,
        const float* __restrict__ v_w, const float* __restrict__ v_b,
        const float* __restrict__ queries) {
    __shared__ float sk[16][16];
    int t = threadIdx.x;
    int s0 = blockIdx.x * 16;
    {
        int sl = t >> 4, j = t & 15;
        int s = s0 + sl;
        float kc = k_b[j], vc = v_b[j];
        for (int d = 0; d < 64; d++) {
            float e = fe_b[d] + pos_emb[s * 64 + d];
            kc = fmaf(e, k_w[d * 16 + j], kc);
            vc = fmaf(e, v_w[d * 16 + j], vc);
        }
        sk[sl][j] = kc;
        g_vc4[j >> 3][(j & 7) >> 1][s >> 1][(s & 1) * 2 + (j & 1)] = vc;
    }
    __syncthreads();
#pragma unroll
    for (int u = 0; u < 4; u++) {
        int item = t + 256 * u;
        int sl = item >> 6, pp = item & 63;
        int g = pp >> 5, p = pp & 31, r = p >> 3, q = p & 7, h = g * 4 + r;
        int s = s0 + sl;
        float acc = 0.f;
#pragma unroll
        for (int j = 0; j < 8; j++) acc = fmaf(queries[q * 64 + h * 8 + j], sk[sl][g * 8 + j], acc);
        g_b4[g][p >> 1][s >> 1][(s & 1) * 2 + (p & 1)] = acc * LOG2E_OVER_SCALE;
    }
}

// --- main: pipelined Z + softmax + attn store + ctx + fused out-proj ---------
__global__ __launch_bounds__(1024, 1) void k_main(const float* __restrict__ x,
                                                  const float* __restrict__ o_w,
                                                  const float* __restrict__ o_b,
                                                  float* __restrict__ out,
                                                  float* __restrict__ attn_out) {
    extern __shared__ float smem[];
    float4* sm_vc = (float4*)smem;                 // [2][4][512] f4  = 64 KB
    float2* sm_x = (float2*)(smem + 16384);        // [2][512] f2    = 8 KB
    float* sm_ow = smem + 16384 + 2048;            // 4096 f         = 16 KB
    float* sm_ctx = sm_ow + 4096;                  // 512 f
    float* sm_iz = sm_ctx + 512;                   // 64 f

    const int tid = threadIdx.x;
    const int w = tid >> 5, lane = tid & 31;
    const int g = w >> 4, wp = w & 15;
    const int p0 = 2 * wp, p1 = p0 + 1;
    const float a0 = g_a[g][p0], a1 = g_a[g][p1];
    const int h0 = g * 4 + (p0 >> 3), q0 = p0 & 7;
    const int h1 = g * 4 + (p1 >> 3), q1 = p1 & 7;

    {   // cache vc (both groups) + o_w in smem
        const float4* vs = (const float4*)&g_vc4[0][0][0][0];
#pragma unroll
        for (int i = 0; i < 4; i++) sm_vc[tid + 1024 * i] = vs[tid + 1024 * i];
        ((float4*)sm_ow)[tid] = ((const float4*)o_w)[tid];
    }
    float bias = 0.f;
    if (tid < 512) bias = o_b[tid & 63];

    const int b0 = blockIdx.x;

    // ---- prologue: Z for first b ----
    if (tid < 256) ((float4*)sm_x)[tid] = ((const float4*)(x + b0 * 1024))[tid];
    __syncthreads();
    {
        float z0 = 0.f, z1 = 0.f;
        const float4* bptr = (const float4*)&g_b4[g][wp][0][0];
#pragma unroll
        for (int i = 0; i < 16; i++) {
            int s2 = 32 * i + lane;
            float4 bb = bptr[s2];
            float2 xv = sm_x[s2];
            z0 += ex2f(fmaf(a0, xv.x, bb.x)) + ex2f(fmaf(a0, xv.y, bb.z));
            z1 += ex2f(fmaf(a1, xv.x, bb.y)) + ex2f(fmaf(a1, xv.y, bb.w));
        }
        z0 = wsum(z0); z1 = wsum(z1);
        if (lane == 0) { sm_iz[g * 32 + p0] = 1.0f / z0; sm_iz[g * 32 + p1] = 1.0f / z1; }
    }

    int cur = 0;
    for (int b = b0; b < 1024; b += 148) {
        const int bn = b + 148;
        if (bn < 1024 && tid < 256)
            ((float4*)&sm_x[(cur ^ 1) * 512])[tid] = ((const float4*)(x + bn * 1024))[tid];
        __syncthreads();   // x-next + sm_iz visible

        const float iz0 = sm_iz[g * 32 + p0];
        const float iz1 = sm_iz[g * 32 + p1];
        const float2* xc = &sm_x[cur * 512];
        const float2* xn = &sm_x[(cur ^ 1) * 512];
        const float4* bptr = (const float4*)&g_b4[g][wp][0][0];
        const float4* vptr = &sm_vc[g * 2048];
        float2* o0 = (float2*)(attn_out + (((size_t)b * 8 + h0) * 8 + q0) * 1024) + lane;
        float2* o1 = (float2*)(attn_out + (((size_t)b * 8 + h1) * 8 + q1) * 1024) + lane;

        float zn0 = 0.f, zn1 = 0.f, xs0 = 0.f, xs1 = 0.f;
        unsigned long long c0[4], c1[4];
#pragma unroll
        for (int k = 0; k < 4; k++) { c0[k] = 0ull; c1[k] = 0ull; }

#pragma unroll
        for (int i = 0; i < 16; i++) {
            int s2 = 32 * i + lane;
            float4 bb = bptr[s2];
            float2 xv = xc[s2];
            float2 xw = xn[s2];

            // Z pipeline for b+148 (reuses bb)
            zn0 += ex2f(fmaf(a0, xw.x, bb.x)) + ex2f(fmaf(a0, xw.y, bb.z));
            zn1 += ex2f(fmaf(a1, xw.x, bb.y)) + ex2f(fmaf(a1, xw.y, bb.w));

            // main work for b
            float e00 = ex2f(fmaf(a0, xv.x, bb.x));
            float e10 = ex2f(fmaf(a1, xv.x, bb.y));
            float e01 = ex2f(fmaf(a0, xv.y, bb.z));
            float e11 = ex2f(fmaf(a1, xv.y, bb.w));

            xs0 = fmaf(e00, xv.x, fmaf(e01, xv.y, xs0));
            xs1 = fmaf(e10, xv.x, fmaf(e11, xv.y, xs1));

            unsigned long long pe00 = pack2(e00, e00), pe01 = pack2(e01, e01);
            unsigned long long pe10 = pack2(e10, e10), pe11 = pack2(e11, e11);
#pragma unroll
            for (int k = 0; k < 4; k++) {
                float4 v4 = vptr[k * 512 + s2];
                unsigned long long vlo = pack2(v4.x, v4.y);
                unsigned long long vhi = pack2(v4.z, v4.w);
                fma2(c0[k], pe00, vlo); fma2(c0[k], pe01, vhi);
                fma2(c1[k], pe10, vlo); fma2(c1[k], pe11, vhi);
            }

            float2 r0, r1;
            r0.x = e00 * iz0; r0.y = e01 * iz0;
            r1.x = e10 * iz1; r1.y = e11 * iz1;
            o0[i * 32] = r0;
            o1[i * 32] = r1;
        }

        // reductions
        zn0 = wsum(zn0); zn1 = wsum(zn1);
        xs0 = wsum(xs0); xs1 = wsum(xs1);
        float cf0[8], cf1[8];
#pragma unroll
        for (int k = 0; k < 4; k++) {
            unpack2(c0[k], cf0[2 * k], cf0[2 * k + 1]);
            unpack2(c1[k], cf1[2 * k], cf1[2 * k + 1]);
        }
#pragma unroll
        for (int j = 0; j < 8; j++) { cf0[j] = wsum(cf0[j]); cf1[j] = wsum(cf1[j]); }

        if (lane == 0) {
#pragma unroll
            for (int j = 0; j < 8; j++) {
                float vwj = g_vw[g][j];
                sm_ctx[q0 * 64 + h0 * 8 + j] = iz0 * fmaf(xs0, vwj, cf0[j]);
                sm_ctx[q1 * 64 + h1 * 8 + j] = iz1 * fmaf(xs1, vwj, cf1[j]);
            }
            sm_iz[g * 32 + p0] = 1.0f / zn0;
            sm_iz[g * 32 + p1] = 1.0f / zn1;
        }
        __syncthreads();

        // fused out-projection: out[b] = ctx @ o_w + o_b
        if (tid < 512) {
            const int q = tid >> 6, e = tid & 63;
            float acc = bias;
            const float4* cr = (const float4*)&sm_ctx[q * 64];
#pragma unroll
            for (int k = 0; k < 16; k++) {
                float4 c4 = cr[k];
                acc = fmaf(c4.x, sm_ow[(4 * k + 0) * 64 + e], acc);
                acc = fmaf(c4.y, sm_ow[(4 * k + 1) * 64 + e], acc);
                acc = fmaf(c4.z, sm_ow[(4 * k + 2) * 64 + e], acc);
                acc = fmaf(c4.w, sm_ow[(4 * k + 3) * 64 + e], acc);
            }
            out[(size_t)b * 512 + tid] = acc;
        }
        cur ^= 1;
    }
}

// ---------------------------------------------------------------------------
extern "C" void kernel_launch(void* const* d_in, const int* in_sizes, int n_in,
                              void* d_out, int out_size) {
    const float* x       = (const float*)d_in[0];
    const float* queries = (const float*)d_in[1];
    const float* fe_w    = (const float*)d_in[2];
    const float* fe_b    = (const float*)d_in[3];
    const float* pos_emb = (const float*)d_in[4];
    const float* k_w     = (const float*)d_in[5];
    const float* k_b     = (const float*)d_in[6];
    const float* v_w     = (const float*)d_in[7];
    const float* v_b     = (const float*)d_in[8];
    const float* o_w     = (const float*)d_in[9];
    const float* o_b     = (const float*)d_in[10];

    float* out  = (float*)d_out;                 // [1024, 512]
    float* attn = out + 1024 * 512;              // [1024, 8, 8, 1024]

    int smem_bytes = (16384 + 2048 + 4096 + 512 + 64) * 4;  // 92,416 B
    cudaFuncSetAttribute(k_main, cudaFuncAttributeMaxDynamicSharedMemorySize, smem_bytes);

    k_pre1<<<1, 64>>>(fe_w, k_w, v_w, queries);
    k_pre2<<<64, 256>>>(fe_b, pos_emb, k_w, k_b, v_w, v_b, queries);
    k_main<<<148, 1024, smem_bytes>>>(x, o_w, o_b, out, attn);
}

// round 5
// speedup vs baseline: 1.9161x; 1.3758x over previous
#include <cuda_runtime.h>

// ---------------------------------------------------------------------------
// GroupedQueryAttention:
//   x_embed affine in scalar x[b,s] => score(log2) = a[g,p]*x[b,s] + bconst[g,p,s]
//   attn = e/Z ; ctx = invZ*(sum_s e*vc[s,:] + (sum_s e*x)*vw) ; out = ctx@o_w+o_b
//
// k_main: grid (74, 2) [g = blockIdx.y], 512 thr / 16 warps, 1 CTA/SM @128 regs.
// Warp wp owns pairs p0=2wp, p1=2wp+1 over the FULL s range; processes NB=2
// batch rows per chunk, so each bconst LDG.128 / vc LDS.128 serves 8 elements.
// Z for the NEXT chunk's 2 rows is computed in the same inner loop (reuses the
// bconst load); inverse-Z values stay in registers. Out-proj fused per chunk.
// Pre-work: single k_pre2 kernel; block 0 additionally computes a[g][p] / vw
// in parallel (replaces the old 15.8us serial k_pre1).
// ---------------------------------------------------------------------------

#define LOG2E_OVER_SCALE ((float)(1.4426950408889634 / 2.8284271247461903))

// g_b4[g][wp][s2][4] = { b(2s2,p0), b(2s2,p1), b(2s2+1,p0), b(2s2+1,p1) }
__device__ __align__(16) float g_b4[2][16][512][4];   // 256 KB
// g_vc4[g][jj][s2][4] = { vc(2s2,2jj), vc(2s2,2jj+1), vc(2s2+1,2jj), vc(2s2+1,2jj+1) }
__device__ __align__(16) float g_vc4[2][4][512][4];   // 64 KB
__device__ float g_a[2][32];
__device__ float g_vw[2][8];

__device__ __forceinline__ float ex2f(float x) {
    float r; asm("ex2.approx.ftz.f32 %0, %1;" : "=f"(r) : "f"(x)); return r;
}
__device__ __forceinline__ unsigned long long pack2(float a, float b) {
    unsigned long long r; asm("mov.b64 %0, {%1, %2};" : "=l"(r) : "f"(a), "f"(b)); return r;
}
__device__ __forceinline__ void unpack2(unsigned long long v, float& a, float& b) {
    asm("mov.b64 {%0, %1}, %2;" : "=f"(a), "=f"(b) : "l"(v));
}
__device__ __forceinline__ void fma2(unsigned long long& d, unsigned long long a, unsigned long long b) {
    asm("fma.rn.f32x2 %0, %1, %2, %0;" : "+l"(d) : "l"(a), "l"(b));
}
__device__ __forceinline__ float wsum(float v) {
#pragma unroll
    for (int m = 16; m > 0; m >>= 1) v += __shfl_xor_sync(0xffffffffu, v, m);
    return v;
}

// --- precompute (single kernel): kc/vc + bconst; block 0 also builds a[], vw --
__global__ __launch_bounds__(256) void k_pre2(
        const float* __restrict__ fe_w,
        const float* __restrict__ fe_b, const float* __restrict__ pos_emb,
        const float* __restrict__ k_w, const float* __restrict__ k_b,
        const float* __restrict__ v_w, const float* __restrict__ v_b,
        const float* __restrict__ queries) {
    __shared__ float sk[16][16];
    __shared__ float s_kw[16];
    int t = threadIdx.x;

    if (blockIdx.x == 0) {
        // parallel replacement for old k_pre1: 16 columns x 16 slices x 4 d's
        int j = t >> 4, sl = t & 15;
        float pk = 0.f, pv = 0.f;
#pragma unroll
        for (int u = 0; u < 4; u++) {
            int d = sl * 4 + u;
            float fw = fe_w[d];
            pk = fmaf(fw, k_w[d * 16 + j], pk);
            pv = fmaf(fw, v_w[d * 16 + j], pv);
        }
#pragma unroll
        for (int m = 8; m > 0; m >>= 1) {
            pk += __shfl_xor_sync(0xffffffffu, pk, m);
            pv += __shfl_xor_sync(0xffffffffu, pv, m);
        }
        if (sl == 0) {
            s_kw[j] = pk;
            g_vw[j >> 3][j & 7] = pv;
        }
        __syncthreads();
        if (t < 64) {
            int g = t >> 5, p = t & 31, r = p >> 3, q = p & 7, h = g * 4 + r;
            float s = 0.f;
#pragma unroll
            for (int j2 = 0; j2 < 8; j2++)
                s = fmaf(queries[q * 64 + h * 8 + j2], s_kw[g * 8 + j2], s);
            g_a[g][p] = s * LOG2E_OVER_SCALE;
        }
        __syncthreads();
    }

    int s0 = blockIdx.x * 16;
    {
        int sl = t >> 4, j = t & 15;
        int s = s0 + sl;
        float kc = k_b[j], vc = v_b[j];
        for (int d = 0; d < 64; d++) {
            float e = fe_b[d] + pos_emb[s * 64 + d];
            kc = fmaf(e, k_w[d * 16 + j], kc);
            vc = fmaf(e, v_w[d * 16 + j], vc);
        }
        sk[sl][j] = kc;
        g_vc4[j >> 3][(j & 7) >> 1][s >> 1][(s & 1) * 2 + (j & 1)] = vc;
    }
    __syncthreads();
#pragma unroll
    for (int u = 0; u < 4; u++) {
        int item = t + 256 * u;
        int sl = item >> 6, pp = item & 63;
        int g = pp >> 5, p = pp & 31, r = p >> 3, q = p & 7, h = g * 4 + r;
        int s = s0 + sl;
        float acc = 0.f;
#pragma unroll
        for (int j = 0; j < 8; j++) acc = fmaf(queries[q * 64 + h * 8 + j], sk[sl][g * 8 + j], acc);
        g_b4[g][p >> 1][s >> 1][(s & 1) * 2 + (p & 1)] = acc * LOG2E_OVER_SCALE;
    }
}

// --- main ---------------------------------------------------------------------
__global__ __launch_bounds__(512, 1) void k_main(const float* __restrict__ x,
                                                 const float* __restrict__ o_w,
                                                 const float* __restrict__ o_b,
                                                 float* __restrict__ out,
                                                 float* __restrict__ attn_out) {
    extern __shared__ float smem[];
    float4* sm_vc = (float4*)smem;                  // [4][512] f4 (group g) = 32 KB
    float2* sm_x = (float2*)(smem + 8192);          // [2 buf][2 rows][512] f2 = 16 KB
    float* sm_ow = smem + 8192 + 8192;              // 4096 f = 16 KB
    float* sm_ctx = sm_ow + 4096;                   // [2][512] = 4 KB

    const int tid = threadIdx.x;
    const int w = tid >> 5, lane = tid & 31;
    const int g = blockIdx.y;
    const int p0 = 2 * w, p1 = p0 + 1;
    const float a0 = g_a[g][p0], a1 = g_a[g][p1];
    const int h0 = g * 4 + (p0 >> 3), q0 = p0 & 7;
    const int h1 = g * 4 + (p1 >> 3), q1 = p1 & 7;

    {   // cache vc (this group) + o_w
        const float4* vs = (const float4*)&g_vc4[g][0][0][0];
#pragma unroll
        for (int i = 0; i < 4; i++) sm_vc[tid + 512 * i] = vs[tid + 512 * i];
        ((float4*)sm_ow)[tid] = ((const float4*)o_w)[tid];
        ((float4*)sm_ow)[tid + 512] = ((const float4*)o_w)[tid + 512];
    }
    const float bias = o_b[tid & 63];

    const int c0 = blockIdx.x;
    const float4* bptr = (const float4*)&g_b4[g][w][0][0];

    // ---- prologue: x + Z for first chunk ----
    ((float4*)sm_x)[tid] = ((const float4*)(x + (size_t)(2 * c0) * 1024))[tid];
    __syncthreads();
    float izA0, izA1, izB0, izB1;
    {
        float zA0 = 0.f, zA1 = 0.f, zB0 = 0.f, zB1 = 0.f;
#pragma unroll
        for (int i = 0; i < 16; i++) {
            int s2 = 32 * i + lane;
            float4 bb = bptr[s2];
            float2 xA = sm_x[s2];
            float2 xB = sm_x[512 + s2];
            zA0 += ex2f(fmaf(a0, xA.x, bb.x)) + ex2f(fmaf(a0, xA.y, bb.z));
            zA1 += ex2f(fmaf(a1, xA.x, bb.y)) + ex2f(fmaf(a1, xA.y, bb.w));
            zB0 += ex2f(fmaf(a0, xB.x, bb.x)) + ex2f(fmaf(a0, xB.y, bb.z));
            zB1 += ex2f(fmaf(a1, xB.x, bb.y)) + ex2f(fmaf(a1, xB.y, bb.w));
        }
        izA0 = 1.0f / wsum(zA0); izA1 = 1.0f / wsum(zA1);
        izB0 = 1.0f / wsum(zB0); izB1 = 1.0f / wsum(zB1);
    }

    int cur = 0;
    for (int c = c0; c < 512; c += 74) {
        const int b0 = 2 * c, b1 = b0 + 1;
        const int cn = c + 74;
        if (cn < 512)
            ((float4*)&sm_x[(cur ^ 1) * 1024])[tid] =
                ((const float4*)(x + (size_t)(2 * cn) * 1024))[tid];
        __syncthreads();   // x-next ready; previous out-proj done reading sm_ctx

        const float2* xc = &sm_x[cur * 1024];
        const float2* xn = &sm_x[(cur ^ 1) * 1024];
        float2* oA0 = (float2*)(attn_out + (((size_t)b0 * 8 + h0) * 8 + q0) * 1024) + lane;
        float2* oA1 = (float2*)(attn_out + (((size_t)b0 * 8 + h1) * 8 + q1) * 1024) + lane;
        float2* oB0 = (float2*)(attn_out + (((size_t)b1 * 8 + h0) * 8 + q0) * 1024) + lane;
        float2* oB1 = (float2*)(attn_out + (((size_t)b1 * 8 + h1) * 8 + q1) * 1024) + lane;

        float znA0 = 0.f, znA1 = 0.f, znB0 = 0.f, znB1 = 0.f;
        float xsA0 = 0.f, xsA1 = 0.f, xsB0 = 0.f, xsB1 = 0.f;
        unsigned long long cA0[4], cA1[4], cB0[4], cB1[4];
#pragma unroll
        for (int k = 0; k < 4; k++) { cA0[k] = cA1[k] = cB0[k] = cB1[k] = 0ull; }

#pragma unroll
        for (int i = 0; i < 16; i++) {
            int s2 = 32 * i + lane;
            float4 bb = bptr[s2];
            float2 xA = xc[s2];
            float2 xB = xc[512 + s2];
            float2 nA = xn[s2];
            float2 nB = xn[512 + s2];

            // Z pipeline for next chunk (reuses bb)
            znA0 += ex2f(fmaf(a0, nA.x, bb.x)) + ex2f(fmaf(a0, nA.y, bb.z));
            znA1 += ex2f(fmaf(a1, nA.x, bb.y)) + ex2f(fmaf(a1, nA.y, bb.w));
            znB0 += ex2f(fmaf(a0, nB.x, bb.x)) + ex2f(fmaf(a0, nB.y, bb.z));
            znB1 += ex2f(fmaf(a1, nB.x, bb.y)) + ex2f(fmaf(a1, nB.y, bb.w));

            // main work, row b0
            float e00 = ex2f(fmaf(a0, xA.x, bb.x));
            float e01 = ex2f(fmaf(a0, xA.y, bb.z));
            float e10 = ex2f(fmaf(a1, xA.x, bb.y));
            float e11 = ex2f(fmaf(a1, xA.y, bb.w));
            // main work, row b1
            float f00 = ex2f(fmaf(a0, xB.x, bb.x));
            float f01 = ex2f(fmaf(a0, xB.y, bb.z));
            float f10 = ex2f(fmaf(a1, xB.x, bb.y));
            float f11 = ex2f(fmaf(a1, xB.y, bb.w));

            xsA0 = fmaf(e00, xA.x, fmaf(e01, xA.y, xsA0));
            xsA1 = fmaf(e10, xA.x, fmaf(e11, xA.y, xsA1));
            xsB0 = fmaf(f00, xB.x, fmaf(f01, xB.y, xsB0));
            xsB1 = fmaf(f10, xB.x, fmaf(f11, xB.y, xsB1));

            unsigned long long pe00 = pack2(e00, e00), pe01 = pack2(e01, e01);
            unsigned long long pe10 = pack2(e10, e10), pe11 = pack2(e11, e11);
            unsigned long long pf00 = pack2(f00, f00), pf01 = pack2(f01, f01);
            unsigned long long pf10 = pack2(f10, f10), pf11 = pack2(f11, f11);
#pragma unroll
            for (int k = 0; k < 4; k++) {
                float4 v4 = sm_vc[k * 512 + s2];
                unsigned long long vlo = pack2(v4.x, v4.y);
                unsigned long long vhi = pack2(v4.z, v4.w);
                fma2(cA0[k], pe00, vlo); fma2(cA0[k], pe01, vhi);
                fma2(cA1[k], pe10, vlo); fma2(cA1[k], pe11, vhi);
                fma2(cB0[k], pf00, vlo); fma2(cB0[k], pf01, vhi);
                fma2(cB1[k], pf10, vlo); fma2(cB1[k], pf11, vhi);
            }

            float2 r;
            r.x = e00 * izA0; r.y = e01 * izA0; __stcs(&oA0[i * 32], r);
            r.x = e10 * izA1; r.y = e11 * izA1; __stcs(&oA1[i * 32], r);
            r.x = f00 * izB0; r.y = f01 * izB0; __stcs(&oB0[i * 32], r);
            r.x = f10 * izB1; r.y = f11 * izB1; __stcs(&oB1[i * 32], r);
        }

        // reductions
        znA0 = wsum(znA0); znA1 = wsum(znA1); znB0 = wsum(znB0); znB1 = wsum(znB1);
        xsA0 = wsum(xsA0); xsA1 = wsum(xsA1); xsB0 = wsum(xsB0); xsB1 = wsum(xsB1);
        float gA0[8], gA1[8], gB0[8], gB1[8];
#pragma unroll
        for (int k = 0; k < 4; k++) {
            unpack2(cA0[k], gA0[2 * k], gA0[2 * k + 1]);
            unpack2(cA1[k], gA1[2 * k], gA1[2 * k + 1]);
            unpack2(cB0[k], gB0[2 * k], gB0[2 * k + 1]);
            unpack2(cB1[k], gB1[2 * k], gB1[2 * k + 1]);
        }
#pragma unroll
        for (int j = 0; j < 8; j++) {
            gA0[j] = wsum(gA0[j]); gA1[j] = wsum(gA1[j]);
            gB0[j] = wsum(gB0[j]); gB1[j] = wsum(gB1[j]);
        }

        if (lane == 0) {
#pragma unroll
            for (int j = 0; j < 8; j++) {
                float vwj = g_vw[g][j];
                sm_ctx[q0 * 64 + h0 * 8 + j]       = izA0 * fmaf(xsA0, vwj, gA0[j]);
                sm_ctx[q1 * 64 + h1 * 8 + j]       = izA1 * fmaf(xsA1, vwj, gA1[j]);
                sm_ctx[512 + q0 * 64 + h0 * 8 + j] = izB0 * fmaf(xsB0, vwj, gB0[j]);
                sm_ctx[512 + q1 * 64 + h1 * 8 + j] = izB1 * fmaf(xsB1, vwj, gB1[j]);
            }
        }
        izA0 = 1.0f / znA0; izA1 = 1.0f / znA1;
        izB0 = 1.0f / znB0; izB1 = 1.0f / znB1;
        __syncthreads();

        // fused out-projection for both rows (each group CTA writes its half of
        // ctx? no: ctx cols span both groups -> only THIS group's 32 head-dims
        // are here. Each (g) CTA computes partial and we need full row.)
        // Solution: each CTA accumulates only its own group's 32 f-dims and the
        // two CTAs write disjoint PARTIALS -> must combine. Instead: ctx dims
        // for group g live at h in [4g,4g+4) -> f in [32g, 32g+32) of each q row.
        // out = sum over f of ctx[f]*o_w[f][e]; split f-range by group and use
        // atomic-free two-pass: CTA g adds its partial via global atomicAdd-free
        // trick: since exactly 2 CTAs contribute, write partial for g=0 and let
        // g=1 add. Simpler and race-free: both CTAs compute over their 32 f's
        // and use atomicAdd. Cost: 512 atomicAdds/b (~negligible vs 64K attn
        // stores). But out is poisoned (0xAA) -> g=0 CTA must WRITE (bias+partial),
        // g=1 must ADD -> ordering race. Use float atomicAdd with out pre-set:
        // avoid by: g==0 writes bias+partial with plain store, then g==1 adds
        // atomically -- race if g1 adds before g0 writes. Instead both atomicAdd
        // and a third step writes bias... No third kernel wanted.
        // Final approach: each CTA handles 256 output elements FULLY by reading
        // the other group's ctx from a global staging buffer? Too complex.
        // Chosen: q-split. CTA g computes FULL out rows for q in [4g, 4g+4),
        // reading the other group's ctx half from global staging written by the
        // other CTA. See g_ctxs staging + spin below.
        {
            // stage this CTA's ctx half to global, signal, then consume peer half
            // (done via simple per-(c,g) flag in global memory)
            ;
        }
        if (tid < 512) { }
        cur ^= 1;
        // --- NOTE: out-projection handled below via staging ---
        // stage ctx halves
        // (implemented after loop for clarity -- see k_outproj)
    }
}

// out-projection as its own kernel: reads g_ctxs staging written by k_main.
// To avoid inter-CTA sync complexity inside k_main, k_main stores full ctx rows
// per (b, group-half) into g_ctxs and this kernel does out = ctx @ o_w + o_b.
__device__ __align__(16) float g_ctxs[1024][8][64];   // 2 MB

__global__ __launch_bounds__(512) void k_outproj(const float* __restrict__ o_w,
                                                 const float* __restrict__ o_b,
                                                 float* __restrict__ out) {
    __shared__ float sw[4096];
    __shared__ float sc[2][512];
    int t = threadIdx.x;
#pragma unroll
    for (int i = 0; i < 8; i++) sw[t + 512 * i] = o_w[t + 512 * i];
    const int q = t >> 6, e = t & 63;
    const float bias = o_b[e];
    int buf = 0;
    for (int b = blockIdx.x; b < 1024; b += 148) {
        sc[buf][t] = ((const float*)g_ctxs)[b * 512 + t];
        __syncthreads();
        float acc = bias;
        const float4* cr = (const float4*)&sc[buf][q * 64];
#pragma unroll
        for (int k = 0; k < 16; k++) {
            float4 c4 = cr[k];
            acc = fmaf(c4.x, sw[(4 * k + 0) * 64 + e], acc);
            acc = fmaf(c4.y, sw[(4 * k + 1) * 64 + e], acc);
            acc = fmaf(c4.z, sw[(4 * k + 2) * 64 + e], acc);
            acc = fmaf(c4.w, sw[(4 * k + 3) * 64 + e], acc);
        }
        out[(size_t)b * 512 + t] = acc;
        buf ^= 1;
    }
}

// k_main writes ctx into g_ctxs instead of doing the projection itself.
// Redefine: patch via a small second pass in k_main's lane0 block -> we instead
// write ctx directly to g_ctxs there. (sm_ctx retained for layout only.)
__global__ __launch_bounds__(512, 1) void k_main2(const float* __restrict__ x,
                                                  float* __restrict__ attn_out) {
    extern __shared__ float smem[];
    float4* sm_vc = (float4*)smem;                  // 32 KB
    float2* sm_x = (float2*)(smem + 8192);          // 16 KB

    const int tid = threadIdx.x;
    const int w = tid >> 5, lane = tid & 31;
    const int g = blockIdx.y;
    const int p0 = 2 * w, p1 = p0 + 1;
    const float a0 = g_a[g][p0], a1 = g_a[g][p1];
    const int h0 = g * 4 + (p0 >> 3), q0 = p0 & 7;
    const int h1 = g * 4 + (p1 >> 3), q1 = p1 & 7;

    {
        const float4* vs = (const float4*)&g_vc4[g][0][0][0];
#pragma unroll
        for (int i = 0; i < 4; i++) sm_vc[tid + 512 * i] = vs[tid + 512 * i];
    }

    const int c0 = blockIdx.x;
    const float4* bptr = (const float4*)&g_b4[g][w][0][0];

    ((float4*)sm_x)[tid] = ((const float4*)(x + (size_t)(2 * c0) * 1024))[tid];
    __syncthreads();
    float izA0, izA1, izB0, izB1;
    {
        float zA0 = 0.f, zA1 = 0.f, zB0 = 0.f, zB1 = 0.f;
#pragma unroll
        for (int i = 0; i < 16; i++) {
            int s2 = 32 * i + lane;
            float4 bb = bptr[s2];
            float2 xA = sm_x[s2];
            float2 xB = sm_x[512 + s2];
            zA0 += ex2f(fmaf(a0, xA.x, bb.x)) + ex2f(fmaf(a0, xA.y, bb.z));
            zA1 += ex2f(fmaf(a1, xA.x, bb.y)) + ex2f(fmaf(a1, xA.y, bb.w));
            zB0 += ex2f(fmaf(a0, xB.x, bb.x)) + ex2f(fmaf(a0, xB.y, bb.z));
            zB1 += ex2f(fmaf(a1, xB.x, bb.y)) + ex2f(fmaf(a1, xB.y, bb.w));
        }
        izA0 = 1.0f / wsum(zA0); izA1 = 1.0f / wsum(zA1);
        izB0 = 1.0f / wsum(zB0); izB1 = 1.0f / wsum(zB1);
    }

    int cur = 0;
    for (int c = c0; c < 512; c += 74) {
        const int b0 = 2 * c, b1 = b0 + 1;
        const int cn = c + 74;
        if (cn < 512)
            ((float4*)&sm_x[(cur ^ 1) * 1024])[tid] =
                ((const float4*)(x + (size_t)(2 * cn) * 1024))[tid];
        __syncthreads();

        const float2* xc = &sm_x[cur * 1024];
        const float2* xn = &sm_x[(cur ^ 1) * 1024];
        float2* oA0 = (float2*)(attn_out + (((size_t)b0 * 8 + h0) * 8 + q0) * 1024) + lane;
        float2* oA1 = (float2*)(attn_out + (((size_t)b0 * 8 + h1) * 8 + q1) * 1024) + lane;
        float2* oB0 = (float2*)(attn_out + (((size_t)b1 * 8 + h0) * 8 + q0) * 1024) + lane;
        float2* oB1 = (float2*)(attn_out + (((size_t)b1 * 8 + h1) * 8 + q1) * 1024) + lane;

        float znA0 = 0.f, znA1 = 0.f, znB0 = 0.f, znB1 = 0.f;
        float xsA0 = 0.f, xsA1 = 0.f, xsB0 = 0.f, xsB1 = 0.f;
        unsigned long long cA0[4], cA1[4], cB0[4], cB1[4];
#pragma unroll
        for (int k = 0; k < 4; k++) { cA0[k] = cA1[k] = cB0[k] = cB1[k] = 0ull; }

#pragma unroll
        for (int i = 0; i < 16; i++) {
            int s2 = 32 * i + lane;
            float4 bb = bptr[s2];
            float2 xA = xc[s2];
            float2 xB = xc[512 + s2];
            float2 nA = xn[s2];
            float2 nB = xn[512 + s2];

            znA0 += ex2f(fmaf(a0, nA.x, bb.x)) + ex2f(fmaf(a0, nA.y, bb.z));
            znA1 += ex2f(fmaf(a1, nA.x, bb.y)) + ex2f(fmaf(a1, nA.y, bb.w));
            znB0 += ex2f(fmaf(a0, nB.x, bb.x)) + ex2f(fmaf(a0, nB.y, bb.z));
            znB1 += ex2f(fmaf(a1, nB.x, bb.y)) + ex2f(fmaf(a1, nB.y, bb.w));

            float e00 = ex2f(fmaf(a0, xA.x, bb.x));
            float e01 = ex2f(fmaf(a0, xA.y, bb.z));
            float e10 = ex2f(fmaf(a1, xA.x, bb.y));
            float e11 = ex2f(fmaf(a1, xA.y, bb.w));
            float f00 = ex2f(fmaf(a0, xB.x, bb.x));
            float f01 = ex2f(fmaf(a0, xB.y, bb.z));
            float f10 = ex2f(fmaf(a1, xB.x, bb.y));
            float f11 = ex2f(fmaf(a1, xB.y, bb.w));

            xsA0 = fmaf(e00, xA.x, fmaf(e01, xA.y, xsA0));
            xsA1 = fmaf(e10, xA.x, fmaf(e11, xA.y, xsA1));
            xsB0 = fmaf(f00, xB.x, fmaf(f01, xB.y, xsB0));
            xsB1 = fmaf(f10, xB.x, fmaf(f11, xB.y, xsB1));

            unsigned long long pe00 = pack2(e00, e00), pe01 = pack2(e01, e01);
            unsigned long long pe10 = pack2(e10, e10), pe11 = pack2(e11, e11);
            unsigned long long pf00 = pack2(f00, f00), pf01 = pack2(f01, f01);
            unsigned long long pf10 = pack2(f10, f10), pf11 = pack2(f11, f11);
#pragma unroll
            for (int k = 0; k < 4; k++) {
                float4 v4 = sm_vc[k * 512 + s2];
                unsigned long long vlo = pack2(v4.x, v4.y);
                unsigned long long vhi = pack2(v4.z, v4.w);
                fma2(cA0[k], pe00, vlo); fma2(cA0[k], pe01, vhi);
                fma2(cA1[k], pe10, vlo); fma2(cA1[k], pe11, vhi);
                fma2(cB0[k], pf00, vlo); fma2(cB0[k], pf01, vhi);
                fma2(cB1[k], pf10, vlo); fma2(cB1[k], pf11, vhi);
            }

            float2 r;
            r.x = e00 * izA0; r.y = e01 * izA0; __stcs(&oA0[i * 32], r);
            r.x = e10 * izA1; r.y = e11 * izA1; __stcs(&oA1[i * 32], r);
            r.x = f00 * izB0; r.y = f01 * izB0; __stcs(&oB0[i * 32], r);
            r.x = f10 * izB1; r.y = f11 * izB1; __stcs(&oB1[i * 32], r);
        }

        znA0 = wsum(znA0); znA1 = wsum(znA1); znB0 = wsum(znB0); znB1 = wsum(znB1);
        xsA0 = wsum(xsA0); xsA1 = wsum(xsA1); xsB0 = wsum(xsB0); xsB1 = wsum(xsB1);
        float gA0[8], gA1[8], gB0[8], gB1[8];
#pragma unroll
        for (int k = 0; k < 4; k++) {
            unpack2(cA0[k], gA0[2 * k], gA0[2 * k + 1]);
            unpack2(cA1[k], gA1[2 * k], gA1[2 * k + 1]);
            unpack2(cB0[k], gB0[2 * k], gB0[2 * k + 1]);
            unpack2(cB1[k], gB1[2 * k], gB1[2 * k + 1]);
        }
#pragma unroll
        for (int j = 0; j < 8; j++) {
            gA0[j] = wsum(gA0[j]); gA1[j] = wsum(gA1[j]);
            gB0[j] = wsum(gB0[j]); gB1[j] = wsum(gB1[j]);
        }

        if (lane == 0) {
#pragma unroll
            for (int j = 0; j < 8; j++) {
                float vwj = g_vw[g][j];
                g_ctxs[b0][q0][h0 * 8 + j] = izA0 * fmaf(xsA0, vwj, gA0[j]);
                g_ctxs[b0][q1][h1 * 8 + j] = izA1 * fmaf(xsA1, vwj, gA1[j]);
                g_ctxs[b1][q0][h0 * 8 + j] = izB0 * fmaf(xsB0, vwj, gB0[j]);
                g_ctxs[b1][q1][h1 * 8 + j] = izB1 * fmaf(xsB1, vwj, gB1[j]);
            }
        }
        izA0 = 1.0f / znA0; izA1 = 1.0f / znA1;
        izB0 = 1.0f / znB0; izB1 = 1.0f / znB1;
        cur ^= 1;
    }
}

// ---------------------------------------------------------------------------
extern "C" void kernel_launch(void* const* d_in, const int* in_sizes, int n_in,
                              void* d_out, int out_size) {
    const float* x       = (const float*)d_in[0];
    const float* queries = (const float*)d_in[1];
    const float* fe_w    = (const float*)d_in[2];
    const float* fe_b    = (const float*)d_in[3];
    const float* pos_emb = (const float*)d_in[4];
    const float* k_w     = (const float*)d_in[5];
    const float* k_b     = (const float*)d_in[6];
    const float* v_w     = (const float*)d_in[7];
    const float* v_b     = (const float*)d_in[8];
    const float* o_w     = (const float*)d_in[9];
    const float* o_b     = (const float*)d_in[10];

    float* out  = (float*)d_out;                 // [1024, 512]
    float* attn = out + 1024 * 512;              // [1024, 8, 8, 1024]

    int smem_bytes = (8192 + 8192) * 4;          // 65,536 B
    cudaFuncSetAttribute(k_main2, cudaFuncAttributeMaxDynamicSharedMemorySize, smem_bytes);

    k_pre2<<<64, 256>>>(fe_w, fe_b, pos_emb, k_w, k_b, v_w, v_b, queries);
    k_main2<<<dim3(74, 2), 512, smem_bytes>>>(x, attn);
    k_outproj<<<148, 512>>>(o_w, o_b, out);
}